// round 14
// baseline (speedup 1.0000x reference)
#include <cuda_runtime.h>

typedef unsigned long long u64;

#define SEQ   20
#define FEAT  5
#define NU1   10
#define NU2   7
#define NU3   4
#define NOUT  4
#define NBATCH 262144
#define NT    128
#define EPB   (NT * 2)          // 2 batch elements per thread
#define TCHUNK 4                // timesteps staged per smem chunk

// ---------------- packed f32x2 helpers ----------------
__device__ __forceinline__ u64 pack2(float lo, float hi) {
    u64 r; asm("mov.b64 %0, {%1, %2};" : "=l"(r) : "f"(lo), "f"(hi)); return r;
}
__device__ __forceinline__ void unpack2(u64 v, float& lo, float& hi) {
    asm("mov.b64 {%0, %1}, %2;" : "=f"(lo), "=f"(hi) : "l"(v));
}
__device__ __forceinline__ u64 ffma2(u64 a, u64 b, u64 c) {
    u64 d; asm("fma.rn.f32x2 %0, %1, %2, %3;" : "=l"(d) : "l"(a), "l"(b), "l"(c)); return d;
}
__device__ __forceinline__ u64 fmul2(u64 a, u64 b) {
    u64 d; asm("mul.rn.f32x2 %0, %1, %2;" : "=l"(d) : "l"(a), "l"(b)); return d;
}
__device__ __forceinline__ float hadd2(u64 v) {
    float a, b; unpack2(v, a, b); return a + b;
}

// ---------------- single-MUFU nonlinearities ----------------
__device__ __forceinline__ float tanh1(float x) {
    float y; asm("tanh.approx.f32 %0, %1;" : "=f"(y) : "f"(x)); return y;
}
// sigmoid(x) = 0.5*tanh(x/2)+0.5 ; the /2 pre-folded into i/f/o weights+bias.
__device__ __forceinline__ float sigf(float zhalf) {
    return fmaf(0.5f, tanh1(zhalf), 0.5f);
}

// ---------------- k-packed weight layout ----------------
// Layer k-row sequences (bias rides a 1.0 multiplicand lane):
//  L1: [x0..x4, 1.0(bias), h1 x10]            KD=16, KP=8,  DP=3 din pairs, PH=5
//  L2: [h1 x10, h2old(7) + 1.0(bias)]         KD=18, KP=9,  DP=5,           PH=4
//  L3: [h2(7)+1.0(bias), h3old x4]            KD=12, KP=6,  DP=4,           PH=2
// smem per (kp,p): 16 floats = [i:float4][f:float4][g:float4][o:float4],
// gate float4 = {w[2kp][u0], w[2kp+1][u0], w[2kp][u1], w[2kp+1][u1]} (pre-scaled)

constexpr int OFF_W1 = 0;      // 8*5*16  = 640
constexpr int OFF_W2 = 640;    // 9*4*16  = 576
constexpr int OFF_W3 = 1216;   // 6*2*16  = 192
constexpr int OFF_WD = 1408;   // 8 pairs -> 16 floats
constexpr int OFF_BD = 1424;   // 4 pairs -> 8 floats
constexpr int OFF_XS = 1432;   // x chunk: [EPB rows][XSTRIDE]
constexpr int XSTRIDE = TCHUNK * 6;                 // 24 floats: (5 feat + 1.0) x 4 ts
constexpr int OFF_CS = OFF_XS + EPB * XSTRIDE;      // 1432 + 6144 = 7576
constexpr int NCPAIR = 11;                          // c pairs/elem: L1 5, L2 4, L3 2
constexpr int SMEM_FLOATS = OFF_CS + 2 * NCPAIR * NT * 2;   // + 5632 = 13208
constexpr int SMEM_BYTES  = SMEM_FLOATS * 4;        // 52832 B (x4 blocks = 211 KB)

constexpr int CP_L1 = 0, CP_L2 = 5, CP_L3 = 9;

// ---------------- weight prep into k-packed smem ----------------
__device__ __forceinline__ void pack_layer(float* dst,
                                           const float* __restrict__ Wk,
                                           const float* __restrict__ Wr,
                                           const float* __restrict__ b,
                                           int wkRows, int biasPos, int wrStart,
                                           int KP, int U, int PH) {
    int total = KP * PH * 16;
    for (int i = threadIdx.x; i < total; i += blockDim.x) {
        int f = i & 3;              // within gate float4
        int g = (i >> 2) & 3;       // gate: 0=i 1=f 2=g 3=o
        int rem = i >> 4;           // kp*PH + p
        int p = rem % PH, kp = rem / PH;
        int j = f >> 1, kk = f & 1;
        int u = 2 * p + j;
        int k = 2 * kp + kk;
        float v = 0.0f;
        if (u < U) {
            float sc = (g == 2) ? 1.0f : 0.5f;
            if (k == biasPos)      v = sc * b[g * U + u];
            else if (k < wkRows)   v = sc * Wk[k * 4 * U + g * U + u];
            else if (k >= wrStart) v = sc * Wr[(k - wrStart) * 4 * U + g * U + u];
        }
        dst[i] = v;
    }
}

// ---------------- k-packed LSTM layer step, 2 elements, gate-halved ----------
// din: previous-layer output pairs (DP u64 per element, packed (v_2k, v_2k+1)).
// h:   this layer's output pairs, updated in place (PH u64 per element).
// FORCE1: hi lane of last pair pinned to 1.0 (bias carrier for next layer).
template<int DP, int PH, bool FORCE1>
__device__ __forceinline__ void layer_stepK(const u64 (&din)[2][DP],
                                            u64 (&h)[2][PH],
                                            u64* __restrict__ cs, int cOff,
                                            const float* __restrict__ w) {
    u64 old[2][PH];
#pragma unroll
    for (int e = 0; e < 2; e++)
#pragma unroll
        for (int i = 0; i < PH; i++) old[e][i] = h[e][i];

#pragma unroll 1
    for (int p = 0; p < PH; p++) {
        const float* wp = w + p * 16;

        // ---- half 0: gates i, f ----
        u64 z[2][4];
        {
            ulonglong2 wi = *(const ulonglong2*)(wp);
            ulonglong2 wf = *(const ulonglong2*)(wp + 4);
#pragma unroll
            for (int e = 0; e < 2; e++) {
                u64 m = din[e][0];
                z[e][0] = fmul2(m, wi.x); z[e][1] = fmul2(m, wi.y);
                z[e][2] = fmul2(m, wf.x); z[e][3] = fmul2(m, wf.y);
            }
        }
#pragma unroll
        for (int kp = 1; kp < DP + PH; kp++) {
            const float* row = wp + kp * PH * 16;
            ulonglong2 wi = *(const ulonglong2*)(row);
            ulonglong2 wf = *(const ulonglong2*)(row + 4);
#pragma unroll
            for (int e = 0; e < 2; e++) {
                u64 m = (kp < DP) ? din[e][kp] : old[e][kp - DP];
                z[e][0] = ffma2(m, wi.x, z[e][0]); z[e][1] = ffma2(m, wi.y, z[e][1]);
                z[e][2] = ffma2(m, wf.x, z[e][2]); z[e][3] = ffma2(m, wf.y, z[e][3]);
            }
        }
        float iv[2][2], fv[2][2];
#pragma unroll
        for (int e = 0; e < 2; e++) {
            iv[e][0] = sigf(hadd2(z[e][0])); iv[e][1] = sigf(hadd2(z[e][1]));
            fv[e][0] = sigf(hadd2(z[e][2])); fv[e][1] = sigf(hadd2(z[e][3]));
        }

        // ---- half 1: gates g, o ----
        u64 y[2][4];
        {
            ulonglong2 wg = *(const ulonglong2*)(wp + 8);
            ulonglong2 wo = *(const ulonglong2*)(wp + 12);
#pragma unroll
            for (int e = 0; e < 2; e++) {
                u64 m = din[e][0];
                y[e][0] = fmul2(m, wg.x); y[e][1] = fmul2(m, wg.y);
                y[e][2] = fmul2(m, wo.x); y[e][3] = fmul2(m, wo.y);
            }
        }
#pragma unroll
        for (int kp = 1; kp < DP + PH; kp++) {
            const float* row = wp + kp * PH * 16;
            ulonglong2 wg = *(const ulonglong2*)(row + 8);
            ulonglong2 wo = *(const ulonglong2*)(row + 12);
#pragma unroll
            for (int e = 0; e < 2; e++) {
                u64 m = (kp < DP) ? din[e][kp] : old[e][kp - DP];
                y[e][0] = ffma2(m, wg.x, y[e][0]); y[e][1] = ffma2(m, wg.y, y[e][1]);
                y[e][2] = ffma2(m, wo.x, y[e][2]); y[e][3] = ffma2(m, wo.y, y[e][3]);
            }
        }

        // ---- pointwise ----
#pragma unroll
        for (int e = 0; e < 2; e++) {
            float g0 = tanh1(hadd2(y[e][0])), g1 = tanh1(hadd2(y[e][1]));
            float o0 = sigf(hadd2(y[e][2])),  o1 = sigf(hadd2(y[e][3]));
            u64 cold = cs[(e * NCPAIR + cOff + p) * NT];
            float c0, c1; unpack2(cold, c0, c1);
            c0 = fmaf(fv[e][0], c0, iv[e][0] * g0);
            c1 = fmaf(fv[e][1], c1, iv[e][1] * g1);
            cs[(e * NCPAIR + cOff + p) * NT] = pack2(c0, c1);
            float h0 = o0 * tanh1(c0);
            float h1 = (FORCE1 && p == PH - 1) ? 1.0f : o1 * tanh1(c1);
            h[e][p] = pack2(h0, h1);
        }
    }
}

// ---------------- fused kernel ----------------
__global__ void __launch_bounds__(NT, 4)
lstm3_kernel(const float* __restrict__ x,
             const float* __restrict__ Wk1, const float* __restrict__ Wr1, const float* __restrict__ b1,
             const float* __restrict__ Wk2, const float* __restrict__ Wr2, const float* __restrict__ b2,
             const float* __restrict__ Wk3, const float* __restrict__ Wr3, const float* __restrict__ b3,
             const float* __restrict__ Wd,  const float* __restrict__ bd,
             float* __restrict__ out) {
    extern __shared__ float s[];

    // weights (k-packed, pre-scaled, bias folded into 1.0-multiplicand rows)
    pack_layer(s + OFF_W1, Wk1, Wr1, b1,  5,  5,  6, 8, NU1, 5);
    pack_layer(s + OFF_W2, Wk2, Wr2, b2, 10, 17, 10, 9, NU2, 4);
    pack_layer(s + OFF_W3, Wk3, Wr3, b3,  7,  7,  8, 6, NU3, 2);
    // dense: wd[kp][o] = (0.5*Wd[2kp][o], 0.5*Wd[2kp+1][o]); bd pairs (0.5*bd, 0)
    for (int i = threadIdx.x; i < 8; i += blockDim.x) {
        int kp = i >> 2, o = i & 3;
        s[OFF_WD + i * 2]     = 0.5f * Wd[(2 * kp) * 4 + o];
        s[OFF_WD + i * 2 + 1] = 0.5f * Wd[(2 * kp + 1) * 4 + o];
    }
    for (int o = threadIdx.x; o < 4; o += blockDim.x) {
        s[OFF_BD + o * 2]     = 0.5f * bd[o];
        s[OFF_BD + o * 2 + 1] = 0.0f;
    }

    const int tid = threadIdx.x;
    float* xs = s + OFF_XS;
    u64* cs = (u64*)(s + OFF_CS) + tid;     // thread-private c columns
    const float* gx = x + (size_t)blockIdx.x * EPB * (SEQ * FEAT);
    const int gidA = blockIdx.x * EPB + tid;
    float* oA = out + (size_t)gidA * (SEQ * NOUT);
    float* oB = oA + (size_t)NT * (SEQ * NOUT);

    // zero own c columns (thread-private, no sync needed)
#pragma unroll
    for (int i = 0; i < 2 * NCPAIR; i++) cs[i * NT] = 0ull;

    // h state as packed pairs; h2 pair3 hi-lane carries the bias 1.0
    u64 h1[2][5], h2[2][4], h3[2][2];
#pragma unroll
    for (int e = 0; e < 2; e++) {
#pragma unroll
        for (int i = 0; i < 5; i++) h1[e][i] = 0ull;
#pragma unroll
        for (int i = 0; i < 4; i++) h2[e][i] = 0ull;
        h2[e][3] = pack2(0.0f, 1.0f);
#pragma unroll
        for (int i = 0; i < 2; i++) h3[e][i] = 0ull;
    }

#pragma unroll 1
    for (int cc = 0; cc < SEQ / TCHUNK; cc++) {
        // stage TCHUNK timesteps: per row, per ts: [x0..x4, 1.0]
        __syncthreads();
        for (int i = tid; i < EPB * XSTRIDE; i += NT) {
            int r = i / XSTRIDE, c = i - r * XSTRIDE;
            int ts = c / 6, j = c - ts * 6;
            float v = 1.0f;
            if (j < FEAT)
                v = gx[r * (SEQ * FEAT) + (cc * TCHUNK + ts) * FEAT + j];
            xs[i] = v;
        }
        __syncthreads();

#pragma unroll 1
        for (int ts = 0; ts < TCHUNK; ts++) {
            int t = cc * TCHUNK + ts;
            // x pairs: (x0,x1),(x2,x3),(x4,1.0) per element
            u64 xp[2][3];
#pragma unroll
            for (int e = 0; e < 2; e++) {
                const float* xr = xs + (e * NT + tid) * XSTRIDE + ts * 6;
#pragma unroll
                for (int kp = 0; kp < 3; kp++)
                    xp[e][kp] = *(const u64*)(xr + kp * 2);
            }

            layer_stepK<3, 5, false>(xp, h1, cs, CP_L1, s + OFF_W1);
            layer_stepK<5, 4, true >(h1, h2, cs, CP_L2, s + OFF_W2);
            layer_stepK<4, 2, false>(h2, h3, cs, CP_L3, s + OFF_W3);

            // dense 4x4 + sigmoid (k-packed over h3 pairs)
#pragma unroll
            for (int e = 0; e < 2; e++) {
                float r[4];
#pragma unroll
                for (int o = 0; o < 4; o++) {
                    u64 z = *(const u64*)(s + OFF_BD + o * 2);
                    z = ffma2(h3[e][0], *(const u64*)(s + OFF_WD + (0 * 4 + o) * 2), z);
                    z = ffma2(h3[e][1], *(const u64*)(s + OFF_WD + (1 * 4 + o) * 2), z);
                    r[o] = sigf(hadd2(z));
                }
                float* op = (e ? oB : oA) + t * NOUT;
                *(float4*)op = make_float4(r[0], r[1], r[2], r[3]);
            }
        }
    }
}

extern "C" void kernel_launch(void* const* d_in, const int* in_sizes, int n_in,
                              void* d_out, int out_size) {
    const float* x   = (const float*)d_in[0];
    const float* Wk1 = (const float*)d_in[1];
    const float* Wr1 = (const float*)d_in[2];
    const float* b1  = (const float*)d_in[3];
    const float* Wk2 = (const float*)d_in[4];
    const float* Wr2 = (const float*)d_in[5];
    const float* b2  = (const float*)d_in[6];
    const float* Wk3 = (const float*)d_in[7];
    const float* Wr3 = (const float*)d_in[8];
    const float* b3  = (const float*)d_in[9];
    const float* Wd  = (const float*)d_in[10];
    const float* bd  = (const float*)d_in[11];

    cudaFuncSetAttribute(lstm3_kernel, cudaFuncAttributeMaxDynamicSharedMemorySize, SMEM_BYTES);

    lstm3_kernel<<<NBATCH / EPB, NT, SMEM_BYTES>>>(
        x, Wk1, Wr1, b1, Wk2, Wr2, b2, Wk3, Wr3, b3, Wd, bd, (float*)d_out);
}

// round 15
// speedup vs baseline: 1.0798x; 1.0798x over previous
#include <cuda_runtime.h>

typedef unsigned long long u64;

#define SEQ   20
#define FEAT  5
#define NU1   10
#define NU2   7
#define NU3   4
#define NOUT  4
#define NBATCH 262144
#define NT    128
#define NELEM 3
#define EPB   (NT * NELEM)                    // 384
#define NBLOCKS ((NBATCH + EPB - 1) / EPB)    // 683 (last block partially valid)
#define TCHUNK 2

// ---------------- packed f32x2 helpers ----------------
__device__ __forceinline__ u64 pack2(float lo, float hi) {
    u64 r; asm("mov.b64 %0, {%1, %2};" : "=l"(r) : "f"(lo), "f"(hi)); return r;
}
__device__ __forceinline__ u64 dup2(float s) {
    u64 r; asm("mov.b64 %0, {%1, %1};" : "=l"(r) : "f"(s)); return r;
}
__device__ __forceinline__ void unpack2(u64 v, float& lo, float& hi) {
    asm("mov.b64 {%0, %1}, %2;" : "=f"(lo), "=f"(hi) : "l"(v));
}
__device__ __forceinline__ u64 ffma2(u64 a, u64 b, u64 c) {
    u64 d; asm("fma.rn.f32x2 %0, %1, %2, %3;" : "=l"(d) : "l"(a), "l"(b), "l"(c)); return d;
}
__device__ __forceinline__ u64 fmul2(u64 a, u64 b) {
    u64 d; asm("mul.rn.f32x2 %0, %1, %2;" : "=l"(d) : "l"(a), "l"(b)); return d;
}

// ---------------- single-MUFU nonlinearities ----------------
__device__ __forceinline__ float tanh1(float x) {
    float y; asm("tanh.approx.f32 %0, %1;" : "=f"(y) : "f"(x)); return y;
}
__device__ __forceinline__ u64 tanh2(u64 v) {
    float a, b; unpack2(v, a, b);
    return pack2(tanh1(a), tanh1(b));
}
// sigmoid(x) = 0.5*tanh(x/2) + 0.5 ; the /2 pre-folded into i/f/o weights.
__device__ __forceinline__ u64 sigh2(u64 zhalf, u64 H2) {
    return ffma2(tanh2(zhalf), H2, H2);
}

// ---------------- shared-memory layout (float offsets, dynamic smem) ----------
constexpr int OFF_W1 = 0;      // 15 rows * 5 PH * 4 g * 2 = 600
constexpr int OFF_B1 = 600;    // 40
constexpr int OFF_W2 = 640;    // 17 * 4 * 4 * 2 = 544 (U2 cols padded 7->8)
constexpr int OFF_B2 = 1184;   // 32
constexpr int OFF_W3 = 1216;   // 11 * 2 * 4 * 2 = 176
constexpr int OFF_B3 = 1392;   // 16
constexpr int OFF_WD = 1408;   // 16
constexpr int OFF_BD = 1424;   // 4
constexpr int OFF_XS = 1428;   // x chunk: [EPB rows][XSTRIDE]
constexpr int XSTRIDE = TCHUNK * FEAT + 1;                  // 11, odd -> conflict-free
constexpr int OFF_CS = OFF_XS + EPB * XSTRIDE;              // 1428 + 4224 = 5652
constexpr int NCPAIR = 11;                                  // c pairs/elem: L1 5, L2 4, L3 2
constexpr int SMEM_FLOATS = OFF_CS + NELEM * NCPAIR * NT * 2;  // + 8448 = 14100
constexpr int SMEM_BYTES  = SMEM_FLOATS * 4;                // 56400 B (x4 = 225.6 KB)

constexpr int CP_L1 = 0, CP_L2 = 5, CP_L3 = 9;

// gate scale: i,f,o get 0.5 (sigmoid-via-tanh), g(cell) gets 1.0
__device__ __forceinline__ float gate_scale(int g) { return (g == 2) ? 1.0f : 0.5f; }

__device__ __forceinline__ void load_wcomb(float* dst, const float* __restrict__ Wk,
                                           const float* __restrict__ Wr,
                                           int D, int U, int PH) {
    int total = (D + U) * PH * 4;
    for (int idx = threadIdx.x; idx < total; idx += blockDim.x) {
        int row = idx / (PH * 4);
        int rem = idx - row * (PH * 4);
        int p = rem >> 2, g = rem & 3;
        const float* src = (row < D) ? (Wk + row * 4 * U) : (Wr + (row - D) * 4 * U);
        float sc = gate_scale(g);
        int u0 = 2 * p, u1 = u0 + 1;
        dst[2 * idx]     = (u0 < U) ? sc * src[g * U + u0] : 0.0f;
        dst[2 * idx + 1] = (u1 < U) ? sc * src[g * U + u1] : 0.0f;
    }
}
__device__ __forceinline__ void load_bias(float* dst, const float* __restrict__ b,
                                          int U, int PH) {
    int total = PH * 4;
    for (int idx = threadIdx.x; idx < total; idx += blockDim.x) {
        int p = idx >> 2, g = idx & 3;
        float sc = gate_scale(g);
        int u0 = 2 * p, u1 = u0 + 1;
        dst[2 * idx]     = (u0 < U) ? sc * b[g * U + u0] : 0.0f;
        dst[2 * idx + 1] = (u1 < U) ? sc * b[g * U + u1] : 0.0f;
    }
}

// ---------------- layer 1: x read from smem (compile-time offsets) ----------
template<int U, int UN, int PH>
__device__ __forceinline__ void layer_stepX(const float* __restrict__ xrow,
                                            float (&h)[NELEM][UN],
                                            u64* __restrict__ cs, int cOff,
                                            const float* __restrict__ w,
                                            const float* __restrict__ bias, u64 H2) {
    constexpr int D = FEAT;
    float old[NELEM][U];
#pragma unroll
    for (int e = 0; e < NELEM; e++)
#pragma unroll
        for (int i = 0; i < U; i++) old[e][i] = h[e][i];

#pragma unroll 1
    for (int p = 0; p < PH; p++) {
        u64 cOld[NELEM];
#pragma unroll
        for (int e = 0; e < NELEM; e++)
            cOld[e] = cs[(e * NCPAIR + cOff + p) * NT];

        u64 zi[NELEM], zf[NELEM];
        {
            ulonglong2 bv = *(const ulonglong2*)(bias + p * 8);
#pragma unroll
            for (int e = 0; e < NELEM; e++) { zi[e] = bv.x; zf[e] = bv.y; }
#pragma unroll
            for (int k = 0; k < D + U; k++) {
                ulonglong2 w0 = *(const ulonglong2*)(w + (k * PH + p) * 8);
#pragma unroll
                for (int e = 0; e < NELEM; e++) {
                    u64 m = dup2((k < D) ? xrow[e * NT * XSTRIDE + k] : old[e][k - D]);
                    zi[e] = ffma2(m, w0.x, zi[e]);
                    zf[e] = ffma2(m, w0.y, zf[e]);
                }
            }
        }
        u64 iv[NELEM], fv[NELEM];
#pragma unroll
        for (int e = 0; e < NELEM; e++) {
            iv[e] = sigh2(zi[e], H2);
            fv[e] = sigh2(zf[e], H2);
        }

        u64 zg[NELEM], zo[NELEM];
        {
            ulonglong2 bv = *(const ulonglong2*)(bias + p * 8 + 4);
#pragma unroll
            for (int e = 0; e < NELEM; e++) { zg[e] = bv.x; zo[e] = bv.y; }
#pragma unroll
            for (int k = 0; k < D + U; k++) {
                ulonglong2 w1 = *(const ulonglong2*)(w + (k * PH + p) * 8 + 4);
#pragma unroll
                for (int e = 0; e < NELEM; e++) {
                    u64 m = dup2((k < D) ? xrow[e * NT * XSTRIDE + k] : old[e][k - D]);
                    zg[e] = ffma2(m, w1.x, zg[e]);
                    zo[e] = ffma2(m, w1.y, zo[e]);
                }
            }
        }
#pragma unroll
        for (int e = 0; e < NELEM; e++) {
            u64 gv = tanh2(zg[e]);
            u64 ov = sigh2(zo[e], H2);
            u64 cn = ffma2(fv[e], cOld[e], fmul2(iv[e], gv));
            cs[(e * NCPAIR + cOff + p) * NT] = cn;
            float hlo, hhi;
            unpack2(fmul2(ov, tanh2(cn)), hlo, hhi);
            h[e][2 * p] = hlo;
            if (2 * p + 1 < U) h[e][2 * p + 1] = hhi;
        }
    }
}

// ---------------- layers 2/3: din from registers ----------------
template<int D, int DN, int U, int UN, int PH>
__device__ __forceinline__ void layer_step3(const float (&din)[NELEM][DN],
                                            float (&h)[NELEM][UN],
                                            u64* __restrict__ cs, int cOff,
                                            const float* __restrict__ w,
                                            const float* __restrict__ bias, u64 H2) {
    float old[NELEM][U];
#pragma unroll
    for (int e = 0; e < NELEM; e++)
#pragma unroll
        for (int i = 0; i < U; i++) old[e][i] = h[e][i];

#pragma unroll 1
    for (int p = 0; p < PH; p++) {
        u64 cOld[NELEM];
#pragma unroll
        for (int e = 0; e < NELEM; e++)
            cOld[e] = cs[(e * NCPAIR + cOff + p) * NT];

        u64 zi[NELEM], zf[NELEM];
        {
            ulonglong2 bv = *(const ulonglong2*)(bias + p * 8);
#pragma unroll
            for (int e = 0; e < NELEM; e++) { zi[e] = bv.x; zf[e] = bv.y; }
#pragma unroll
            for (int k = 0; k < D + U; k++) {
                ulonglong2 w0 = *(const ulonglong2*)(w + (k * PH + p) * 8);
#pragma unroll
                for (int e = 0; e < NELEM; e++) {
                    u64 m = dup2((k < D) ? din[e][k] : old[e][k - D]);
                    zi[e] = ffma2(m, w0.x, zi[e]);
                    zf[e] = ffma2(m, w0.y, zf[e]);
                }
            }
        }
        u64 iv[NELEM], fv[NELEM];
#pragma unroll
        for (int e = 0; e < NELEM; e++) {
            iv[e] = sigh2(zi[e], H2);
            fv[e] = sigh2(zf[e], H2);
        }

        u64 zg[NELEM], zo[NELEM];
        {
            ulonglong2 bv = *(const ulonglong2*)(bias + p * 8 + 4);
#pragma unroll
            for (int e = 0; e < NELEM; e++) { zg[e] = bv.x; zo[e] = bv.y; }
#pragma unroll
            for (int k = 0; k < D + U; k++) {
                ulonglong2 w1 = *(const ulonglong2*)(w + (k * PH + p) * 8 + 4);
#pragma unroll
                for (int e = 0; e < NELEM; e++) {
                    u64 m = dup2((k < D) ? din[e][k] : old[e][k - D]);
                    zg[e] = ffma2(m, w1.x, zg[e]);
                    zo[e] = ffma2(m, w1.y, zo[e]);
                }
            }
        }
#pragma unroll
        for (int e = 0; e < NELEM; e++) {
            u64 gv = tanh2(zg[e]);
            u64 ov = sigh2(zo[e], H2);
            u64 cn = ffma2(fv[e], cOld[e], fmul2(iv[e], gv));
            cs[(e * NCPAIR + cOff + p) * NT] = cn;
            float hlo, hhi;
            unpack2(fmul2(ov, tanh2(cn)), hlo, hhi);
            h[e][2 * p] = hlo;
            if (2 * p + 1 < U) h[e][2 * p + 1] = hhi;
        }
    }
}

// ---------------- fused kernel ----------------
__global__ void __launch_bounds__(NT, 4)
lstm3_kernel(const float* __restrict__ x,
             const float* __restrict__ Wk1, const float* __restrict__ Wr1, const float* __restrict__ b1,
             const float* __restrict__ Wk2, const float* __restrict__ Wr2, const float* __restrict__ b2,
             const float* __restrict__ Wk3, const float* __restrict__ Wr3, const float* __restrict__ b3,
             const float* __restrict__ Wd,  const float* __restrict__ bd,
             float* __restrict__ out) {
    extern __shared__ float s[];

    load_wcomb(s + OFF_W1, Wk1, Wr1, FEAT, NU1, 5);
    load_bias (s + OFF_B1, b1, NU1, 5);
    load_wcomb(s + OFF_W2, Wk2, Wr2, NU1, NU2, 4);
    load_bias (s + OFF_B2, b2, NU2, 4);
    load_wcomb(s + OFF_W3, Wk3, Wr3, NU2, NU3, 2);
    load_bias (s + OFF_B3, b3, NU3, 2);
    for (int idx = threadIdx.x; idx < 8; idx += blockDim.x) {
        int k = idx >> 1, p = idx & 1;
        s[OFF_WD + 2 * idx]     = 0.5f * Wd[k * 4 + 2 * p];
        s[OFF_WD + 2 * idx + 1] = 0.5f * Wd[k * 4 + 2 * p + 1];
    }
    for (int idx = threadIdx.x; idx < 4; idx += blockDim.x)
        s[OFF_BD + idx] = 0.5f * bd[idx];

    const int tid = threadIdx.x;
    const u64 H2 = pack2(0.5f, 0.5f);
    const int blockBase = blockIdx.x * EPB;
    float* xs = s + OFF_XS;
    u64* cs = (u64*)(s + OFF_CS) + tid;

    // zero c-state in smem
    {
        u64* cz = (u64*)(s + OFF_CS);
        for (int i = tid; i < NELEM * NCPAIR * NT; i += NT) cz[i] = 0ull;
    }

    // h state: scalars in registers (h2 unpadded: 7)
    float h1[NELEM][NU1], h2[NELEM][NU2], h3[NELEM][NU3];
#pragma unroll
    for (int e = 0; e < NELEM; e++) {
#pragma unroll
        for (int i = 0; i < NU1; i++) h1[e][i] = 0.0f;
#pragma unroll
        for (int i = 0; i < NU2; i++) h2[e][i] = 0.0f;
#pragma unroll
        for (int i = 0; i < NU3; i++) h3[e][i] = 0.0f;
    }

#pragma unroll 1
    for (int cc = 0; cc < SEQ / TCHUNK; cc++) {
        // stage TCHUNK timesteps of x for all EPB rows (clamped; masked at store)
        __syncthreads();
        for (int i = tid; i < EPB * XSTRIDE; i += NT) {
            int r = i / XSTRIDE, col = i - r * XSTRIDE;
            int grow = blockBase + r;
            if (grow >= NBATCH) grow = NBATCH - 1;
            float v = 0.0f;
            if (col < TCHUNK * FEAT)
                v = x[(size_t)grow * (SEQ * FEAT) + cc * (TCHUNK * FEAT) + col];
            xs[i] = v;
        }
        __syncthreads();

#pragma unroll
        for (int ts = 0; ts < TCHUNK; ts++) {
            const float* xrow = xs + tid * XSTRIDE + ts * FEAT;

            layer_stepX<NU1, NU1, 5>(xrow, h1, cs, CP_L1, s + OFF_W1, s + OFF_B1, H2);
            layer_step3<NU1, NU1, NU2, NU2, 4>(h1, h2, cs, CP_L2, s + OFF_W2, s + OFF_B2, H2);
            layer_step3<NU2, NU2, NU3, NU3, 2>(h2, h3, cs, CP_L3, s + OFF_W3, s + OFF_B3, H2);

            // dense 4x4 + sigmoid (weights pre-halved)
            int t = cc * TCHUNK + ts;
            ulonglong2 bdv = *(const ulonglong2*)(s + OFF_BD);
#pragma unroll
            for (int e = 0; e < NELEM; e++) {
                u64 z0 = bdv.x, z1 = bdv.y;
#pragma unroll
                for (int k = 0; k < NU3; k++) {
                    u64 m = dup2(h3[e][k]);
                    ulonglong2 w = *(const ulonglong2*)(s + OFF_WD + k * 4);
                    z0 = ffma2(m, w.x, z0);
                    z1 = ffma2(m, w.y, z1);
                }
                u64 r0 = sigh2(z0, H2), r1 = sigh2(z1, H2);
                float o0, o1, o2, o3;
                unpack2(r0, o0, o1);
                unpack2(r1, o2, o3);
                int gid = blockBase + e * NT + tid;
                if (gid < NBATCH)
                    *(float4*)(out + (size_t)gid * (SEQ * NOUT) + t * NOUT) =
                        make_float4(o0, o1, o2, o3);
            }
        }
    }
}

extern "C" void kernel_launch(void* const* d_in, const int* in_sizes, int n_in,
                              void* d_out, int out_size) {
    const float* x   = (const float*)d_in[0];
    const float* Wk1 = (const float*)d_in[1];
    const float* Wr1 = (const float*)d_in[2];
    const float* b1  = (const float*)d_in[3];
    const float* Wk2 = (const float*)d_in[4];
    const float* Wr2 = (const float*)d_in[5];
    const float* b2  = (const float*)d_in[6];
    const float* Wk3 = (const float*)d_in[7];
    const float* Wr3 = (const float*)d_in[8];
    const float* b3  = (const float*)d_in[9];
    const float* Wd  = (const float*)d_in[10];
    const float* bd  = (const float*)d_in[11];

    cudaFuncSetAttribute(lstm3_kernel, cudaFuncAttributeMaxDynamicSharedMemorySize, SMEM_BYTES);

    lstm3_kernel<<<NBLOCKS, NT, SMEM_BYTES>>>(
        x, Wk1, Wr1, b1, Wk2, Wr2, b2, Wk3, Wr3, b3, Wd, bd, (float*)d_out);
}

// round 16
// speedup vs baseline: 1.2485x; 1.1562x over previous
#include <cuda_runtime.h>

typedef unsigned long long u64;

#define SEQ   20
#define FEAT  5
#define NU1   10
#define NU2   7
#define NU3   4
#define NOUT  4
#define NBATCH 262144
#define NTHREADS 128
#define EPB (NTHREADS * 2)      // 2 batch elements per thread
#define TCHUNK 5                // timesteps staged per smem chunk

// ---------------- packed f32x2 helpers ----------------
__device__ __forceinline__ u64 pack2(float lo, float hi) {
    u64 r; asm("mov.b64 %0, {%1, %2};" : "=l"(r) : "f"(lo), "f"(hi)); return r;
}
__device__ __forceinline__ u64 dup2(float s) {
    u64 r; asm("mov.b64 %0, {%1, %1};" : "=l"(r) : "f"(s)); return r;
}
__device__ __forceinline__ void unpack2(u64 v, float& lo, float& hi) {
    asm("mov.b64 {%0, %1}, %2;" : "=f"(lo), "=f"(hi) : "l"(v));
}
__device__ __forceinline__ u64 ffma2(u64 a, u64 b, u64 c) {
    u64 d; asm("fma.rn.f32x2 %0, %1, %2, %3;" : "=l"(d) : "l"(a), "l"(b), "l"(c)); return d;
}
__device__ __forceinline__ u64 fmul2(u64 a, u64 b) {
    u64 d; asm("mul.rn.f32x2 %0, %1, %2;" : "=l"(d) : "l"(a), "l"(b)); return d;
}

// ---------------- single-MUFU nonlinearities ----------------
__device__ __forceinline__ float tanh1(float x) {
    float y; asm("tanh.approx.f32 %0, %1;" : "=f"(y) : "f"(x)); return y;
}
__device__ __forceinline__ u64 tanh2(u64 v) {
    float a, b; unpack2(v, a, b);
    return pack2(tanh1(a), tanh1(b));
}
// sigmoid(x) = 0.5*tanh(x/2) + 0.5 ; the /2 pre-folded into i/f/o weights.
__device__ __forceinline__ u64 sigh2(u64 zhalf, u64 H2) {
    return ffma2(tanh2(zhalf), H2, H2);
}

// ---------------- shared-memory layout (float offsets, dynamic smem) ----------
constexpr int OFF_W1 = 0;      // 15 rows * 5 PH * 4 g * 2 = 600
constexpr int OFF_B1 = 600;    // 40
constexpr int OFF_W2 = 640;    // 17 * 4 * 4 * 2 = 544 (U2 cols padded 7->8)
constexpr int OFF_B2 = 1184;   // 32
constexpr int OFF_W3 = 1216;   // 11 * 2 * 4 * 2 = 176
constexpr int OFF_B3 = 1392;   // 16
constexpr int OFF_WD = 1408;   // 16
constexpr int OFF_BD = 1424;   // 4
constexpr int OFF_XS = 1428;   // x chunk: [EPB rows][TCHUNK*FEAT cols]
constexpr int XCOLS  = TCHUNK * FEAT;                       // 25
constexpr int OFF_CS = OFF_XS + EPB * XCOLS;                // c-state: 22 pairs x NT u64
constexpr int NCPAIR = 11;                                  // 5 + 4 + 2 pairs per element
constexpr int SMEM_FLOATS = OFF_CS + 2 * NCPAIR * NTHREADS * 2;
constexpr int SMEM_BYTES  = SMEM_FLOATS * 4;                // 53,840 B (x4 = 215 KB)

constexpr int CP_L1 = 0, CP_L2 = 5, CP_L3 = 9;

// gate scale: i,f,o get 0.5 (sigmoid-via-tanh), g(cell) gets 1.0
__device__ __forceinline__ float gate_scale(int g) { return (g == 2) ? 1.0f : 0.5f; }

__device__ __forceinline__ void load_wcomb(float* dst, const float* __restrict__ Wk,
                                           const float* __restrict__ Wr,
                                           int D, int U, int PH) {
    int total = (D + U) * PH * 4;
    for (int idx = threadIdx.x; idx < total; idx += blockDim.x) {
        int row = idx / (PH * 4);
        int rem = idx - row * (PH * 4);
        int p = rem >> 2, g = rem & 3;
        const float* src = (row < D) ? (Wk + row * 4 * U) : (Wr + (row - D) * 4 * U);
        float sc = gate_scale(g);
        int u0 = 2 * p, u1 = u0 + 1;
        dst[2 * idx]     = (u0 < U) ? sc * src[g * U + u0] : 0.0f;
        dst[2 * idx + 1] = (u1 < U) ? sc * src[g * U + u1] : 0.0f;
    }
}
__device__ __forceinline__ void load_bias(float* dst, const float* __restrict__ b,
                                          int U, int PH) {
    int total = PH * 4;
    for (int idx = threadIdx.x; idx < total; idx += blockDim.x) {
        int p = idx >> 2, g = idx & 3;
        float sc = gate_scale(g);
        int u0 = 2 * p, u1 = u0 + 1;
        dst[2 * idx]     = (u0 < U) ? sc * b[g * U + u0] : 0.0f;
        dst[2 * idx + 1] = (u1 < U) ? sc * b[g * U + u1] : 0.0f;
    }
}

// ---------------- LSTM layer step: 2 elements share every weight load --------
// p-loop NOT unrolled (contains register pressure); k-loop fully unrolled.
// c-state lives in smem (thread-private columns).
template<int D, int U, int PH>
__device__ __forceinline__ void layer_step2(const float* __restrict__ dA,
                                            const float* __restrict__ dB,
                                            float* __restrict__ hA, float* __restrict__ hB,
                                            u64* __restrict__ csA, u64* __restrict__ csB,
                                            const float* __restrict__ w,
                                            const float* __restrict__ bias, u64 H2) {
    float oldA[U], oldB[U];
#pragma unroll
    for (int i = 0; i < U; i++) { oldA[i] = hA[i]; oldB[i] = hB[i]; }

#pragma unroll 1
    for (int p = 0; p < PH; p++) {
        u64 cOldA = csA[p * NTHREADS];
        u64 cOldB = csB[p * NTHREADS];
        ulonglong2 bv0 = *(const ulonglong2*)(bias + p * 8);
        ulonglong2 bv1 = *(const ulonglong2*)(bias + p * 8 + 4);
        u64 zaA = bv0.x, zfA = bv0.y, zgA = bv1.x, zoA = bv1.y;
        u64 zaB = bv0.x, zfB = bv0.y, zgB = bv1.x, zoB = bv1.y;
        const float* wp = w + p * 8;
#pragma unroll
        for (int k = 0; k < D + U; k++) {
            float sA = (k < D) ? dA[k] : oldA[k - D];
            float sB = (k < D) ? dB[k] : oldB[k - D];
            u64 mA = dup2(sA);
            u64 mB = dup2(sB);
            const float* row = wp + k * PH * 8;
            ulonglong2 w0 = *(const ulonglong2*)(row);
            ulonglong2 w1 = *(const ulonglong2*)(row + 4);
            zaA = ffma2(mA, w0.x, zaA); zfA = ffma2(mA, w0.y, zfA);
            zgA = ffma2(mA, w1.x, zgA); zoA = ffma2(mA, w1.y, zoA);
            zaB = ffma2(mB, w0.x, zaB); zfB = ffma2(mB, w0.y, zfB);
            zgB = ffma2(mB, w1.x, zgB); zoB = ffma2(mB, w1.y, zoB);
        }
        {
            u64 iv = sigh2(zaA, H2), fv = sigh2(zfA, H2), gv = tanh2(zgA), ov = sigh2(zoA, H2);
            u64 cn = ffma2(fv, cOldA, fmul2(iv, gv));
            csA[p * NTHREADS] = cn;
            u64 hn = fmul2(ov, tanh2(cn));
            unpack2(hn, hA[2 * p], hA[2 * p + 1]);
        }
        {
            u64 iv = sigh2(zaB, H2), fv = sigh2(zfB, H2), gv = tanh2(zgB), ov = sigh2(zoB, H2);
            u64 cn = ffma2(fv, cOldB, fmul2(iv, gv));
            csB[p * NTHREADS] = cn;
            u64 hn = fmul2(ov, tanh2(cn));
            unpack2(hn, hB[2 * p], hB[2 * p + 1]);
        }
    }
}

// ---------------- fused kernel ----------------
__global__ void __launch_bounds__(NTHREADS, 4)
lstm3_kernel(const float* __restrict__ x,
             const float* __restrict__ Wk1, const float* __restrict__ Wr1, const float* __restrict__ b1,
             const float* __restrict__ Wk2, const float* __restrict__ Wr2, const float* __restrict__ b2,
             const float* __restrict__ Wk3, const float* __restrict__ Wr3, const float* __restrict__ b3,
             const float* __restrict__ Wd,  const float* __restrict__ bd,
             float* __restrict__ out) {
    extern __shared__ float s[];

    load_wcomb(s + OFF_W1, Wk1, Wr1, FEAT, NU1, 5);
    load_bias (s + OFF_B1, b1, NU1, 5);
    load_wcomb(s + OFF_W2, Wk2, Wr2, NU1, NU2, 4);
    load_bias (s + OFF_B2, b2, NU2, 4);
    load_wcomb(s + OFF_W3, Wk3, Wr3, NU2, NU3, 2);
    load_bias (s + OFF_B3, b3, NU3, 2);
    for (int idx = threadIdx.x; idx < 8; idx += blockDim.x) {
        int k = idx >> 1, p = idx & 1;
        s[OFF_WD + 2 * idx]     = 0.5f * Wd[k * 4 + 2 * p];
        s[OFF_WD + 2 * idx + 1] = 0.5f * Wd[k * 4 + 2 * p + 1];
    }
    for (int idx = threadIdx.x; idx < 4; idx += blockDim.x)
        s[OFF_BD + idx] = 0.5f * bd[idx];
    __syncthreads();   // the ONLY block barrier: weights visible to all warps

    const int tid = threadIdx.x;
    const int wid = tid >> 5;
    const u64 H2 = pack2(0.5f, 0.5f);
    const float* gx = x + (size_t)blockIdx.x * EPB * (SEQ * FEAT);
    float* xs = s + OFF_XS;
    u64* cs = (u64*)(s + OFF_CS);
    u64* csA = cs + tid;                          // element A's c bank (own column)
    u64* csB = cs + NCPAIR * NTHREADS + tid;      // element B's c bank (own column)

    // zero own c columns (thread-private, no sync needed)
#pragma unroll
    for (int i = 0; i < NCPAIR; i++) { csA[i * NTHREADS] = 0ull; csB[i * NTHREADS] = 0ull; }

    const int gidA = blockIdx.x * EPB + tid;
    float* oA = out + (size_t)gidA * (SEQ * NOUT);
    float* oB = oA + (size_t)NTHREADS * (SEQ * NOUT);

    // h state: scalars in registers
    float h1A[NU1], h1B[NU1], h2A[8], h2B[8], h3A[NU3], h3B[NU3];
#pragma unroll
    for (int i = 0; i < NU1; i++) { h1A[i] = h1B[i] = 0.0f; }
#pragma unroll
    for (int i = 0; i < 8; i++)   { h2A[i] = h2B[i] = 0.0f; }
#pragma unroll
    for (int i = 0; i < NU3; i++) { h3A[i] = h3B[i] = 0.0f; }

#pragma unroll 1
    for (int cc = 0; cc < SEQ / TCHUNK; cc++) {
        // warp-private x staging: warp w owns rows [32w,32w+32) and [128+32w,128+32w+32),
        // exactly the rows its own threads consume -> __syncwarp suffices, no block barrier.
        __syncwarp();
        {
            const int lane = tid & 31;
            const int rbase0 = wid * 32;            // A rows of this warp
            const int rbase1 = 128 + wid * 32;      // B rows of this warp
            for (int i = lane; i < 32 * XCOLS; i += 32) {
                int rl = i / XCOLS, col = i - rl * XCOLS;
                int r0 = rbase0 + rl, r1 = rbase1 + rl;
                xs[r0 * XCOLS + col] = gx[r0 * (SEQ * FEAT) + cc * XCOLS + col];
                xs[r1 * XCOLS + col] = gx[r1 * (SEQ * FEAT) + cc * XCOLS + col];
            }
        }
        __syncwarp();

#pragma unroll
        for (int ts = 0; ts < TCHUNK; ts++) {
            int t = cc * TCHUNK + ts;
            const float* xA = xs + tid * XCOLS + ts * FEAT;
            const float* xB = xA + NTHREADS * XCOLS;

            layer_step2<FEAT, NU1, 5>(xA,  xB,  h1A, h1B,
                                      csA + CP_L1 * NTHREADS, csB + CP_L1 * NTHREADS,
                                      s + OFF_W1, s + OFF_B1, H2);
            layer_step2<NU1,  NU2, 4>(h1A, h1B, h2A, h2B,
                                      csA + CP_L2 * NTHREADS, csB + CP_L2 * NTHREADS,
                                      s + OFF_W2, s + OFF_B2, H2);
            layer_step2<NU2,  NU3, 2>(h2A, h2B, h3A, h3B,
                                      csA + CP_L3 * NTHREADS, csB + CP_L3 * NTHREADS,
                                      s + OFF_W3, s + OFF_B3, H2);

            // dense 4x4 + sigmoid (weights pre-halved)
            ulonglong2 bdv = *(const ulonglong2*)(s + OFF_BD);
#pragma unroll
            for (int e = 0; e < 2; e++) {
                const float* h3 = e ? h3B : h3A;
                u64 z0 = bdv.x, z1 = bdv.y;
#pragma unroll
                for (int k = 0; k < NU3; k++) {
                    u64 m = dup2(h3[k]);
                    ulonglong2 w = *(const ulonglong2*)(s + OFF_WD + k * 4);
                    z0 = ffma2(m, w.x, z0);
                    z1 = ffma2(m, w.y, z1);
                }
                u64 r0 = sigh2(z0, H2), r1 = sigh2(z1, H2);
                float o0, o1, o2, o3;
                unpack2(r0, o0, o1);
                unpack2(r1, o2, o3);
                float* op = (e ? oB : oA) + t * NOUT;
                *(float4*)op = make_float4(o0, o1, o2, o3);
            }
        }
    }
}

extern "C" void kernel_launch(void* const* d_in, const int* in_sizes, int n_in,
                              void* d_out, int out_size) {
    const float* x   = (const float*)d_in[0];
    const float* Wk1 = (const float*)d_in[1];
    const float* Wr1 = (const float*)d_in[2];
    const float* b1  = (const float*)d_in[3];
    const float* Wk2 = (const float*)d_in[4];
    const float* Wr2 = (const float*)d_in[5];
    const float* b2  = (const float*)d_in[6];
    const float* Wk3 = (const float*)d_in[7];
    const float* Wr3 = (const float*)d_in[8];
    const float* b3  = (const float*)d_in[9];
    const float* Wd  = (const float*)d_in[10];
    const float* bd  = (const float*)d_in[11];

    cudaFuncSetAttribute(lstm3_kernel, cudaFuncAttributeMaxDynamicSharedMemorySize, SMEM_BYTES);

    lstm3_kernel<<<NBATCH / EPB, NTHREADS, SMEM_BYTES>>>(
        x, Wk1, Wr1, b1, Wk2, Wr2, b2, Wk3, Wr3, b3, Wd, bd, (float*)d_out);
}